// round 14
// baseline (speedup 1.0000x reference)
#include <cuda_runtime.h>
#include <cuda_bf16.h>
#include <cstdint>

#define LL 2048
#define DD 64
#define NBH 32
#define TM 128
#define TN 64
#define NIT (LL/TN)    // 32
#define PSTR 72        // padded row stride in halves (144B)

// dynamic smem byte offsets
#define QHI_B   0u
#define QLO_B   18432u
#define KV_B    36864u          // two K/V buffers, each 36864B
#define KVSTRIDE 36864u
#define KHI_O   0u              // offsets within a KV buffer
#define KLO_O   9216u
#define VHI_O   18432u
#define VLO_O   27648u
#define RS_B    110592u
#define MB_B    111104u         // valid bitmask, double buffered: 2 x 256 x uint32
#define SM_TOTAL 113152u

__device__ float g_inv[NBH * LL];
// pre-split K/V (bf16 hi/lo), identity layout: [bh][row][64]
__device__ __nv_bfloat16 g_khi[NBH*LL*DD];
__device__ __nv_bfloat16 g_klo[NBH*LL*DD];
__device__ __nv_bfloat16 g_vhi[NBH*LL*DD];
__device__ __nv_bfloat16 g_vlo[NBH*LL*DD];

__device__ __forceinline__ uint32_t smem_u32(const void* p){
    uint32_t a;
    asm("{ .reg .u64 t; cvta.to.shared.u64 t, %1; cvt.u32.u64 %0, t; }" : "=r"(a) : "l"(p));
    return a;
}
__device__ __forceinline__ float fex2(float x){
    float r;
    asm("ex2.approx.f32 %0, %1;" : "=f"(r) : "f"(x));
    return r;
}
__device__ __forceinline__ void cpasync16(uint32_t saddr, const void* gaddr){
    asm volatile("cp.async.cg.shared.global [%0], [%1], 16;" :: "r"(saddr), "l"(gaddr) : "memory");
}
__device__ __forceinline__ void ldsm4(uint32_t* r, uint32_t a){
    asm volatile("ldmatrix.sync.aligned.m8n8.x4.shared.b16 {%0,%1,%2,%3}, [%4];"
        : "=r"(r[0]),"=r"(r[1]),"=r"(r[2]),"=r"(r[3]) : "r"(a));
}
__device__ __forceinline__ void mma16816(float* c, const uint32_t* a, const uint32_t* b){
    asm volatile("mma.sync.aligned.m16n8k16.row.col.f32.bf16.bf16.f32 "
        "{%0,%1,%2,%3}, {%4,%5,%6,%7}, {%8,%9}, {%0,%1,%2,%3};"
        : "+f"(c[0]),"+f"(c[1]),"+f"(c[2]),"+f"(c[3])
        : "r"(a[0]),"r"(a[1]),"r"(a[2]),"r"(a[3]),"r"(b[0]),"r"(b[1]));
}
__device__ __forceinline__ uint32_t packbf(__nv_bfloat16 a, __nv_bfloat16 b){
    return ((uint32_t)__bfloat16_as_ushort(b)<<16)|(uint32_t)__bfloat16_as_ushort(a);
}
__device__ __forceinline__ void split2(float a, float b, uint32_t& hi, uint32_t& lo){
    __nv_bfloat16 ha=__float2bfloat16(a), hb=__float2bfloat16(b);
    hi = packbf(ha,hb);
    lo = packbf(__float2bfloat16(a-__bfloat162float(ha)),
                __float2bfloat16(b-__bfloat162float(hb)));
}
__device__ __forceinline__ void split_store(char* hi, char* lo, uint32_t off, float4 x){
    uint32_t h0,l0,h1,l1;
    split2(x.x,x.y,h0,l0); split2(x.z,x.w,h1,l1);
    *(uint2*)(hi+off) = make_uint2(h0,h1);
    *(uint2*)(lo+off) = make_uint2(l0,l1);
}

// Coalesced valid->bitmask packer (unchanged from r10).
__device__ __forceinline__ void pack_mask_tile(const int* validb, int kb,
                                               uint32_t* dstbuf, int tid, int l){
    #pragma unroll
    for (int j=0;j<8;j++){
        int i = tid + j*256;
        int row = i >> 4, seg = i & 15;
        const int4 x = *(const int4*)(validb + (size_t)row*LL + kb + seg*4);
        uint32_t nib = (x.x>0?1u:0u)|(x.y>0?2u:0u)|(x.z>0?4u:0u)|(x.w>0?8u:0u);
        uint32_t word = nib << ((seg & 7) * 4);
        word |= __shfl_xor_sync(0xffffffffu, word, 1);
        word |= __shfl_xor_sync(0xffffffffu, word, 2);
        word |= __shfl_xor_sync(0xffffffffu, word, 4);
        if ((l & 7) == 0) dstbuf[row*2 + (seg>>3)] = word;
    }
}

// pre-split K and V into bf16 hi/lo gmem arrays (identity layout)
__global__ __launch_bounds__(256) void preconv_kernel(
    const float* __restrict__ k, const float* __restrict__ v)
{
    size_t i = (size_t)blockIdx.x * blockDim.x + threadIdx.x;   // float4 index
    float4 kx = ((const float4*)k)[i];
    float4 vx = ((const float4*)v)[i];
    uint32_t h0,l0,h1,l1;
    split2(kx.x,kx.y,h0,l0); split2(kx.z,kx.w,h1,l1);
    ((uint2*)g_khi)[i] = make_uint2(h0,h1);
    ((uint2*)g_klo)[i] = make_uint2(l0,l1);
    split2(vx.x,vx.y,h0,l0); split2(vx.z,vx.w,h1,l1);
    ((uint2*)g_vhi)[i] = make_uint2(h0,h1);
    ((uint2*)g_vlo)[i] = make_uint2(l0,l1);
}

__global__ __launch_bounds__(256,2) void attn_mma(
    const float* __restrict__ q, const int* __restrict__ valid,
    const float* __restrict__ scale_p,
    float* __restrict__ res, float* __restrict__ attw)
{
    extern __shared__ char smem[];
    const uint32_t sb = smem_u32(smem);
    const int tid = threadIdx.x, w = tid>>5, l = tid&31;
    const int bh = blockIdx.y, q0 = blockIdx.x*TM;
    const float scale2 = (*scale_p) * 1.44269504088896f;   // fold log2(e)
    float* rowsum = (float*)(smem + RS_B);
    uint32_t* maskbuf = (uint32_t*)(smem + MB_B);   // [2][256]
    if (tid < TM) rowsum[tid] = 0.f;

    // ---- cp.async chunk mapping: 512 16B-chunks per 8KB array-tile ----
    const uint32_t c0chunk = (uint32_t)tid;           // chunks tid and tid+256
    const uint32_t so0 = (c0chunk>>3)*144u + (c0chunk&7)*16u;
    const uint32_t so1 = ((c0chunk+256u)>>3)*144u + ((c0chunk+256u)&7)*16u;
    const uint32_t go0 = c0chunk*16u, go1 = (c0chunk+256u)*16u;

    const char* khi_g = (const char*)(g_khi + (size_t)bh*LL*DD);
    const char* klo_g = (const char*)(g_klo + (size_t)bh*LL*DD);
    const char* vhi_g = (const char*)(g_vhi + (size_t)bh*LL*DD);
    const char* vlo_g = (const char*)(g_vlo + (size_t)bh*LL*DD);

    // ---- prologue: cp.async tile 0 -> buf0 ----
    {
        const uint32_t kv0 = sb + KV_B;
        cpasync16(kv0+KHI_O+so0, khi_g+go0); cpasync16(kv0+KHI_O+so1, khi_g+go1);
        cpasync16(kv0+KLO_O+so0, klo_g+go0); cpasync16(kv0+KLO_O+so1, klo_g+go1);
        cpasync16(kv0+VHI_O+so0, vhi_g+go0); cpasync16(kv0+VHI_O+so1, vhi_g+go1);
        cpasync16(kv0+VLO_O+so0, vlo_g+go0); cpasync16(kv0+VLO_O+so1, vlo_g+go1);
        asm volatile("cp.async.commit_group;" ::: "memory");
    }

    // ---- Q load + bf16 hi/lo split ----
    const float4* qsrc = (const float4*)(q + ((size_t)bh*LL+q0)*DD);
    #pragma unroll
    for (int j=0;j<8;j++){
        int i = tid + j*256;
        int row = i>>4, c4 = (i&15)*4;
        split_store(smem+QHI_B, smem+QLO_B, (uint32_t)(row*PSTR+c4)*2u, qsrc[i]);
    }

    const int* validb = valid + ((size_t)bh*LL+q0)*LL;
    float* attwb = attw + ((size_t)bh*LL+q0)*LL;

    // ---- per-lane ldmatrix offsets ----
    const int bg = l>>3, blr = l&7;
    const uint32_t qa_off = (uint32_t)((w*16 + (l&15))*PSTR + (l>>4)*8)*2u;  // A frag
    uint32_t kb_off[4], vb_off[4];
    #pragma unroll
    for (int p=0;p<4;p++){
        kb_off[p] = (uint32_t)((p*16 + (bg>>1)*8 + blr)*PSTR + (bg&1)*8)*2u;   // K B-frag
        vb_off[p] = (uint32_t)(((bg&1)*8 + blr)*PSTR + p*16 + (bg>>1)*8)*2u;   // V B-frag (trans)
    }

    float ofr[8][4];
    #pragma unroll
    for(int n=0;n<8;n++){
        #pragma unroll
        for(int i=0;i<4;i++) ofr[n][i]=0.f;
    }
    float lp0 = 0.f, lp1 = 0.f;

    // ---- mask tile 0 ----
    pack_mask_tile(validb, 0, maskbuf, tid, l);

    asm volatile("cp.async.wait_group 0;" ::: "memory");
    __syncthreads();

    // ---- persistent Q-LO fragments (16 regs; Q-lo smem never re-read) ----
    uint32_t qfL[4][4];
    #pragma unroll
    for (int ksI=0; ksI<4; ++ksI)
        ldsm4(qfL[ksI], sb + QLO_B + qa_off + ksI*32);

    const int r0 = w*16 + (l>>2);   // this thread's first S/O row

    #pragma unroll 2
    for (int it=0; it<NIT; ++it){
        const int kb = it*TN;
        const int buf = it & 1;
        const uint32_t kvb = sb + KV_B + (uint32_t)buf*KVSTRIDE;       // current (read)
        const uint32_t kvn = sb + KV_B + (uint32_t)(buf^1)*KVSTRIDE;   // next (write)
        const bool have_next = (it+1 < NIT);

        // ---- issue next-tile cp.async (no regs, no scoreboard) ----
        if (have_next){
            const uint32_t gb = (uint32_t)(kb+TN)*DD*2u;   // byte offset of next tile
            cpasync16(kvn+KHI_O+so0, khi_g+gb+go0); cpasync16(kvn+KHI_O+so1, khi_g+gb+go1);
            cpasync16(kvn+KLO_O+so0, klo_g+gb+go0); cpasync16(kvn+KLO_O+so1, klo_g+gb+go1);
            cpasync16(kvn+VHI_O+so0, vhi_g+gb+go0); cpasync16(kvn+VHI_O+so1, vhi_g+gb+go1);
            cpasync16(kvn+VLO_O+so0, vlo_g+gb+go0); cpasync16(kvn+VLO_O+so1, vlo_g+gb+go1);
            asm volatile("cp.async.commit_group;" ::: "memory");
        }

        // ---- S = Q K^T, bf16x3 (Q-lo from registers) ----
        float sf[8][4];
        #pragma unroll
        for(int n=0;n<8;n++){
            #pragma unroll
            for(int i=0;i<4;i++) sf[n][i]=0.f;
        }
        #pragma unroll
        for (int ksI=0; ksI<4; ++ksI){
            uint32_t aH[4];
            ldsm4(aH, sb + QHI_B + qa_off + ksI*32);
            #pragma unroll
            for (int p=0;p<4;p++){
                uint32_t bH[4], bL[4];
                ldsm4(bH, kvb + KHI_O + kb_off[p] + ksI*32);
                ldsm4(bL, kvb + KLO_O + kb_off[p] + ksI*32);
                #pragma unroll
                for (int nn=0;nn<2;nn++){
                    const int n = p*2+nn;
                    mma16816(sf[n], aH, &bH[nn*2]);
                    mma16816(sf[n], aH, &bL[nn*2]);
                    mma16816(sf[n], qfL[ksI], &bH[nn*2]);
                }
            }
        }

        // ---- prefetch next mask (LDG hidden under epilogue+PV) ----
        if (have_next)
            pack_mask_tile(validb, kb + TN, maskbuf + (buf^1)*256, tid, l);

        // ---- epilogue: mask + exp + attw store + pack P into registers ----
        uint32_t pH[8][2], pL[8][2];
        {
            const uint32_t mk0a = maskbuf[buf*256 + r0*2];
            const uint32_t mk0b = maskbuf[buf*256 + r0*2 + 1];
            const uint32_t mk1a = maskbuf[buf*256 + (r0+8)*2];
            const uint32_t mk1b = maskbuf[buf*256 + (r0+8)*2 + 1];
            #pragma unroll
            for (int n=0;n<8;n++){
                const int cl = n*8 + (l&3)*2;
                const uint32_t mk0 = (n<4)?mk0a:mk0b;
                const uint32_t mk1 = (n<4)?mk1a:mk1b;
                const int sh = cl & 31;
                float e00 = (mk0>>sh)&1u     ? fex2(sf[n][0]*scale2) : 0.f;
                float e01 = (mk0>>(sh+1))&1u ? fex2(sf[n][1]*scale2) : 0.f;
                float e10 = (mk1>>sh)&1u     ? fex2(sf[n][2]*scale2) : 0.f;
                float e11 = (mk1>>(sh+1))&1u ? fex2(sf[n][3]*scale2) : 0.f;
                lp0 += e00+e01; lp1 += e10+e11;
                *(float2*)(attwb + (size_t)r0*LL + kb + cl)     = make_float2(e00,e01);
                *(float2*)(attwb + (size_t)(r0+8)*LL + kb + cl) = make_float2(e10,e11);
                split2(e00,e01,pH[n][0],pL[n][0]);
                split2(e10,e11,pH[n][1],pL[n][1]);
            }
        }

        // ---- O += P V, bf16x3 (P from registers, V via ldmatrix.trans) ----
        #pragma unroll
        for (int g=0;g<4;g++){
            uint32_t aPh[4] = {pH[2*g][0], pH[2*g][1], pH[2*g+1][0], pH[2*g+1][1]};
            uint32_t aPl[4] = {pL[2*g][0], pL[2*g][1], pL[2*g+1][0], pL[2*g+1][1]};
            #pragma unroll
            for (int p=0;p<4;p++){
                uint32_t vH[4], vL[4];
                asm volatile("ldmatrix.sync.aligned.m8n8.x4.trans.shared.b16 {%0,%1,%2,%3}, [%4];"
                    : "=r"(vH[0]),"=r"(vH[1]),"=r"(vH[2]),"=r"(vH[3])
                    : "r"(kvb + VHI_O + vb_off[p] + g*2304));
                asm volatile("ldmatrix.sync.aligned.m8n8.x4.trans.shared.b16 {%0,%1,%2,%3}, [%4];"
                    : "=r"(vL[0]),"=r"(vL[1]),"=r"(vL[2]),"=r"(vL[3])
                    : "r"(kvb + VLO_O + vb_off[p] + g*2304));
                #pragma unroll
                for (int nn=0;nn<2;nn++){
                    const int n = p*2+nn;
                    mma16816(ofr[n], aPh, &vH[nn*2]);
                    mma16816(ofr[n], aPh, &vL[nn*2]);
                    mma16816(ofr[n], aPl, &vH[nn*2]);
                }
            }
        }

        if (have_next)
            asm volatile("cp.async.wait_group 0;" ::: "memory");
        __syncthreads();   // buf consumed by all warps; buf^1 fully written
    }

    // ---- row-sum reduction -> inverse ----
    {
        float x0 = lp0, x1 = lp1;
        x0 += __shfl_xor_sync(0xffffffffu, x0, 1);
        x0 += __shfl_xor_sync(0xffffffffu, x0, 2);
        x1 += __shfl_xor_sync(0xffffffffu, x1, 1);
        x1 += __shfl_xor_sync(0xffffffffu, x1, 2);
        if ((l&3)==0){
            rowsum[r0]   = x0;
            rowsum[r0+8] = x1;
        }
    }
    __syncthreads();
    if (tid < TM){
        float s_ = rowsum[tid];
        float inv = s_>0.f ? 1.f/s_ : 0.f;
        g_inv[bh*LL + q0 + tid] = inv;
        rowsum[tid] = inv;
    }
    __syncthreads();

    // ---- normalized result write ----
    float* resb = res + ((size_t)bh*LL+q0)*DD;
    {
        float i0 = rowsum[r0], i1 = rowsum[r0+8];
        #pragma unroll
        for (int n=0;n<8;n++){
            const int dc = n*8 + (l&3)*2;
            *(float2*)(resb + (size_t)r0*DD + dc)     = make_float2(ofr[n][0]*i0, ofr[n][1]*i0);
            *(float2*)(resb + (size_t)(r0+8)*DD + dc) = make_float2(ofr[n][2]*i1, ofr[n][3]*i1);
        }
    }
}

// scale att_w rows by 1/l (att_w was written unnormalized)
__global__ __launch_bounds__(256) void fixup_kernel(float* __restrict__ attw)
{
    size_t idx = (size_t)blockIdx.x * blockDim.x + threadIdx.x;   // float4 index
    float inv = g_inv[idx >> 9];
    float4* p = (float4*)attw + idx;
    float4 val = *p;
    val.x *= inv; val.y *= inv; val.z *= inv; val.w *= inv;
    *p = val;
}

extern "C" void kernel_launch(void* const* d_in, const int* in_sizes, int n_in,
                              void* d_out, int out_size)
{
    const float* q     = (const float*)d_in[0];
    const float* k     = (const float*)d_in[1];
    const float* v     = (const float*)d_in[2];
    const int*   valid = (const int*)  d_in[3];
    const float* scale = (const float*)d_in[4];

    float* res  = (float*)d_out;                      // [B,H,L,D]
    float* attw = res + (size_t)NBH * LL * DD;        // [B,H,L,L]

    cudaFuncSetAttribute(attn_mma, cudaFuncAttributeMaxDynamicSharedMemorySize, SM_TOTAL);

    // 1) pre-split K/V to bf16 hi/lo (64MB traffic, ~11us)
    preconv_kernel<<<(NBH*(size_t)LL*DD/4)/256, 256>>>(k, v);
    // 2) attention
    dim3 grid(LL / TM, NBH);   // (16, 32)
    attn_mma<<<grid, 256, SM_TOTAL>>>(q, valid, scale, res, attw);
    // 3) normalize attw
    fixup_kernel<<<(NBH * (size_t)LL * LL / 4) / 256, 256>>>(attw);
}

// round 15
// speedup vs baseline: 1.1063x; 1.1063x over previous
#include <cuda_runtime.h>
#include <cuda_bf16.h>
#include <cstdint>

#define LL 2048
#define DD 64
#define NBH 32
#define TM 128
#define TN 64
#define NIT (LL/TN)    // 32
#define PSTR 72        // padded row stride in halves (144B)

// dynamic smem byte offsets
#define QHI_B   0u
#define QLO_B   18432u
#define KV_B    36864u          // two K/V buffers, each 36864B
#define KVSTRIDE 36864u
#define KHI_O   0u              // offsets within a KV buffer
#define KLO_O   9216u
#define VHI_O   18432u
#define VLO_O   27648u
#define RS_B    110592u
#define MB_B    111104u         // valid bitmask, double buffered: 2 x 256 x uint32
#define SM_TOTAL 113152u

__device__ float g_inv[NBH * LL];

__device__ __forceinline__ uint32_t smem_u32(const void* p){
    uint32_t a;
    asm("{ .reg .u64 t; cvta.to.shared.u64 t, %1; cvt.u32.u64 %0, t; }" : "=r"(a) : "l"(p));
    return a;
}
__device__ __forceinline__ float fex2(float x){
    float r;
    asm("ex2.approx.f32 %0, %1;" : "=f"(r) : "f"(x));
    return r;
}
__device__ __forceinline__ void ldsm4(uint32_t* r, uint32_t a){
    asm volatile("ldmatrix.sync.aligned.m8n8.x4.shared.b16 {%0,%1,%2,%3}, [%4];"
        : "=r"(r[0]),"=r"(r[1]),"=r"(r[2]),"=r"(r[3]) : "r"(a));
}
__device__ __forceinline__ void ldsm4t(uint32_t* r, uint32_t a){
    asm volatile("ldmatrix.sync.aligned.m8n8.x4.trans.shared.b16 {%0,%1,%2,%3}, [%4];"
        : "=r"(r[0]),"=r"(r[1]),"=r"(r[2]),"=r"(r[3]) : "r"(a));
}
__device__ __forceinline__ void mma16816(float* c, const uint32_t* a, const uint32_t* b){
    asm volatile("mma.sync.aligned.m16n8k16.row.col.f32.bf16.bf16.f32 "
        "{%0,%1,%2,%3}, {%4,%5,%6,%7}, {%8,%9}, {%0,%1,%2,%3};"
        : "+f"(c[0]),"+f"(c[1]),"+f"(c[2]),"+f"(c[3])
        : "r"(a[0]),"r"(a[1]),"r"(a[2]),"r"(a[3]),"r"(b[0]),"r"(b[1]));
}
__device__ __forceinline__ uint32_t packbf(__nv_bfloat16 a, __nv_bfloat16 b){
    return ((uint32_t)__bfloat16_as_ushort(b)<<16)|(uint32_t)__bfloat16_as_ushort(a);
}
__device__ __forceinline__ void split2(float a, float b, uint32_t& hi, uint32_t& lo){
    __nv_bfloat16 ha=__float2bfloat16(a), hb=__float2bfloat16(b);
    hi = packbf(ha,hb);
    lo = packbf(__float2bfloat16(a-__bfloat162float(ha)),
                __float2bfloat16(b-__bfloat162float(hb)));
}
__device__ __forceinline__ void split_store(char* hi, char* lo, uint32_t off, float4 x){
    uint32_t h0,l0,h1,l1;
    split2(x.x,x.y,h0,l0); split2(x.z,x.w,h1,l1);
    *(uint2*)(hi+off) = make_uint2(h0,h1);
    *(uint2*)(lo+off) = make_uint2(l0,l1);
}

// Coalesced valid->bitmask packer; streaming loads (__ldcs) — valid is
// single-use, evict-first keeps L2 for the shared K/V working set.
__device__ __forceinline__ void pack_mask_tile(const int* validb, int kb,
                                               uint32_t* dstbuf, int tid, int l){
    #pragma unroll
    for (int j=0;j<8;j++){
        int i = tid + j*256;
        int row = i >> 4, seg = i & 15;
        const int4 x = __ldcs((const int4*)(validb + (size_t)row*LL + kb + seg*4));
        uint32_t nib = (x.x>0?1u:0u)|(x.y>0?2u:0u)|(x.z>0?4u:0u)|(x.w>0?8u:0u);
        uint32_t word = nib << ((seg & 7) * 4);
        word |= __shfl_xor_sync(0xffffffffu, word, 1);
        word |= __shfl_xor_sync(0xffffffffu, word, 2);
        word |= __shfl_xor_sync(0xffffffffu, word, 4);
        if ((l & 7) == 0) dstbuf[row*2 + (seg>>3)] = word;
    }
}

__global__ __launch_bounds__(256,2) void attn_mma(
    const float* __restrict__ q, const float* __restrict__ k,
    const float* __restrict__ v, const int* __restrict__ valid,
    const float* __restrict__ scale_p,
    float* __restrict__ res, float* __restrict__ attw)
{
    extern __shared__ char smem[];
    const uint32_t sb = smem_u32(smem);
    const int tid = threadIdx.x, w = tid>>5, l = tid&31;
    const int bh = blockIdx.y, q0 = blockIdx.x*TM;
    const float scale2 = (*scale_p) * 1.44269504088896f;   // fold log2(e)
    float* rowsum = (float*)(smem + RS_B);
    uint32_t* maskbuf = (uint32_t*)(smem + MB_B);   // [2][256]
    if (tid < TM) rowsum[tid] = 0.f;

    // ---- Q load + bf16 hi/lo split ----
    const float4* qsrc = (const float4*)(q + ((size_t)bh*LL+q0)*DD);
    #pragma unroll
    for (int j=0;j<8;j++){
        int i = tid + j*256;
        int row = i>>4, c4 = (i&15)*4;
        split_store(smem+QHI_B, smem+QLO_B, (uint32_t)(row*PSTR+c4)*2u, qsrc[i]);
    }

    const float* kbh_ = k + (size_t)bh*LL*DD;
    const float* vbh_ = v + (size_t)bh*LL*DD;
    const int* validb = valid + ((size_t)bh*LL+q0)*LL;
    float* attwb = attw + ((size_t)bh*LL+q0)*LL;

    // ---- per-lane ldmatrix offsets ----
    const int bg = l>>3, blr = l&7;
    const uint32_t qa_off = (uint32_t)((w*16 + (l&15))*PSTR + (l>>4)*8)*2u;  // A frag
    uint32_t kb_off[4], vb_off[4];
    #pragma unroll
    for (int p=0;p<4;p++){
        kb_off[p] = (uint32_t)((p*16 + (bg>>1)*8 + blr)*PSTR + (bg&1)*8)*2u;   // K B-frag
        vb_off[p] = (uint32_t)(((bg&1)*8 + blr)*PSTR + p*16 + (bg>>1)*8)*2u;   // V B-frag (trans)
    }

    // ---- K/V tile loader mapping ----
    const uint32_t ldoff = (uint32_t)((tid>>4)*PSTR+(tid&15)*4)*2u;

    float ofr[8][4];
    #pragma unroll
    for(int n=0;n<8;n++){
        #pragma unroll
        for(int i=0;i<4;i++) ofr[n][i]=0.f;
    }
    float lp0 = 0.f, lp1 = 0.f;

    // ---- prologue: K/V tile 0 -> buf0, mask tile 0 -> maskbuf[0] ----
    {
        char* kv0 = smem + KV_B;
        const float4* ks_ = (const float4*)kbh_;
        const float4* vs_ = (const float4*)vbh_;
        #pragma unroll
        for (int j=0;j<4;j++){
            uint32_t off = ldoff + (uint32_t)(j*16*PSTR)*2u;
            split_store(kv0+KHI_O, kv0+KLO_O, off, ks_[tid + j*256]);
            split_store(kv0+VHI_O, kv0+VLO_O, off, vs_[tid + j*256]);
        }
        pack_mask_tile(validb, 0, maskbuf, tid, l);
    }
    __syncthreads();

    const int r0 = w*16 + (l>>2);   // this thread's first S/O row

    #pragma unroll 1
    for (int it=0; it<NIT; ++it){
        const int kb = it*TN;
        const int buf = it & 1;
        const uint32_t kvb = sb + KV_B + (uint32_t)buf*KVSTRIDE;     // current (read)
        char*          kvn = smem + KV_B + (buf^1)*KVSTRIDE;        // next (write)
        const bool have_next = (it+1 < NIT);

        // ---- issue next-K LDG (transient) ----
        float4 kreg[4];
        if (have_next){
            const float4* ks_ = (const float4*)(kbh_ + (size_t)(kb+TN)*DD);
            #pragma unroll
            for (int j=0;j<4;j++) kreg[j] = ks_[tid + j*256];
        }

        // ---- S = Q K^T, bf16x3 ----
        float sf[8][4];
        #pragma unroll
        for(int n=0;n<8;n++){
            #pragma unroll
            for(int i=0;i<4;i++) sf[n][i]=0.f;
        }
        #pragma unroll
        for (int ksI=0; ksI<4; ++ksI){
            uint32_t aH[4], aL[4];
            ldsm4(aH, sb + QHI_B + qa_off + ksI*32);
            ldsm4(aL, sb + QLO_B + qa_off + ksI*32);
            #pragma unroll
            for (int p=0;p<4;p++){
                uint32_t bH[4], bL[4];
                ldsm4(bH, kvb + KHI_O + kb_off[p] + ksI*32);
                ldsm4(bL, kvb + KLO_O + kb_off[p] + ksI*32);
                #pragma unroll
                for (int nn=0;nn<2;nn++){
                    const int n = p*2+nn;
                    mma16816(sf[n], aH, &bH[nn*2]);
                    mma16816(sf[n], aH, &bL[nn*2]);
                    mma16816(sf[n], aL, &bH[nn*2]);
                }
            }
        }

        // ---- store next-K, issue next-V LDG, prefetch next mask ----
        float4 vreg[4];
        if (have_next){
            #pragma unroll
            for (int j=0;j<4;j++)
                split_store(kvn+KHI_O, kvn+KLO_O, ldoff + (uint32_t)(j*16*PSTR)*2u, kreg[j]);
            const float4* vs_ = (const float4*)(vbh_ + (size_t)(kb+TN)*DD);
            #pragma unroll
            for (int j=0;j<4;j++) vreg[j] = vs_[tid + j*256];
            pack_mask_tile(validb, kb + TN, maskbuf + (buf^1)*256, tid, l);
        }

        // ---- epilogue: mask + exp + attw store (streaming) + pack P ----
        uint32_t pH[8][2], pL[8][2];
        {
            const uint32_t mk0a = maskbuf[buf*256 + r0*2];
            const uint32_t mk0b = maskbuf[buf*256 + r0*2 + 1];
            const uint32_t mk1a = maskbuf[buf*256 + (r0+8)*2];
            const uint32_t mk1b = maskbuf[buf*256 + (r0+8)*2 + 1];
            #pragma unroll
            for (int n=0;n<8;n++){
                const int cl = n*8 + (l&3)*2;
                const uint32_t mk0 = (n<4)?mk0a:mk0b;
                const uint32_t mk1 = (n<4)?mk1a:mk1b;
                const int sh = cl & 31;
                float e00 = (mk0>>sh)&1u     ? fex2(sf[n][0]*scale2) : 0.f;
                float e01 = (mk0>>(sh+1))&1u ? fex2(sf[n][1]*scale2) : 0.f;
                float e10 = (mk1>>sh)&1u     ? fex2(sf[n][2]*scale2) : 0.f;
                float e11 = (mk1>>(sh+1))&1u ? fex2(sf[n][3]*scale2) : 0.f;
                lp0 += e00+e01; lp1 += e10+e11;
                __stcs((float2*)(attwb + (size_t)r0*LL + kb + cl),     make_float2(e00,e01));
                __stcs((float2*)(attwb + (size_t)(r0+8)*LL + kb + cl), make_float2(e10,e11));
                split2(e00,e01,pH[n][0],pL[n][0]);
                split2(e10,e11,pH[n][1],pL[n][1]);
            }
        }

        // ---- store next-V ----
        if (have_next){
            #pragma unroll
            for (int j=0;j<4;j++)
                split_store(kvn+VHI_O, kvn+VLO_O, ldoff + (uint32_t)(j*16*PSTR)*2u, vreg[j]);
        }

        // ---- O += P V, bf16x3 (P from registers, V via ldmatrix.trans) ----
        #pragma unroll
        for (int g=0;g<4;g++){
            uint32_t aPh[4] = {pH[2*g][0], pH[2*g][1], pH[2*g+1][0], pH[2*g+1][1]};
            uint32_t aPl[4] = {pL[2*g][0], pL[2*g][1], pL[2*g+1][0], pL[2*g+1][1]};
            #pragma unroll
            for (int p=0;p<4;p++){
                uint32_t vH[4], vL[4];
                ldsm4t(vH, kvb + VHI_O + vb_off[p] + g*2304);   // 16 key rows * 144B
                ldsm4t(vL, kvb + VLO_O + vb_off[p] + g*2304);
                #pragma unroll
                for (int nn=0;nn<2;nn++){
                    const int n = p*2+nn;
                    mma16816(ofr[n], aPh, &vH[nn*2]);
                    mma16816(ofr[n], aPh, &vL[nn*2]);
                    mma16816(ofr[n], aPl, &vH[nn*2]);
                }
            }
        }

        __syncthreads();   // buf consumed by all warps; buf^1 fully written
    }

    // ---- row-sum reduction -> inverse ----
    {
        float x0 = lp0, x1 = lp1;
        x0 += __shfl_xor_sync(0xffffffffu, x0, 1);
        x0 += __shfl_xor_sync(0xffffffffu, x0, 2);
        x1 += __shfl_xor_sync(0xffffffffu, x1, 1);
        x1 += __shfl_xor_sync(0xffffffffu, x1, 2);
        if ((l&3)==0){
            rowsum[r0]   = x0;
            rowsum[r0+8] = x1;
        }
    }
    __syncthreads();
    if (tid < TM){
        float s_ = rowsum[tid];
        float inv = s_>0.f ? 1.f/s_ : 0.f;
        g_inv[bh*LL + q0 + tid] = inv;
        rowsum[tid] = inv;
    }
    __syncthreads();

    // ---- normalized result write ----
    float* resb = res + ((size_t)bh*LL+q0)*DD;
    {
        float i0 = rowsum[r0], i1 = rowsum[r0+8];
        #pragma unroll
        for (int n=0;n<8;n++){
            const int dc = n*8 + (l&3)*2;
            *(float2*)(resb + (size_t)r0*DD + dc)     = make_float2(ofr[n][0]*i0, ofr[n][1]*i0);
            *(float2*)(resb + (size_t)(r0+8)*DD + dc) = make_float2(ofr[n][2]*i1, ofr[n][3]*i1);
        }
    }
}

// scale att_w rows by 1/l (att_w was written unnormalized); pure streaming
__global__ __launch_bounds__(256) void fixup_kernel(float* __restrict__ attw)
{
    size_t idx = (size_t)blockIdx.x * blockDim.x + threadIdx.x;   // float4 index
    float inv = g_inv[idx >> 9];
    float4* p = (float4*)attw + idx;
    float4 val = __ldcs(p);
    val.x *= inv; val.y *= inv; val.z *= inv; val.w *= inv;
    __stcs(p, val);
}

extern "C" void kernel_launch(void* const* d_in, const int* in_sizes, int n_in,
                              void* d_out, int out_size)
{
    const float* q     = (const float*)d_in[0];
    const float* k     = (const float*)d_in[1];
    const float* v     = (const float*)d_in[2];
    const int*   valid = (const int*)  d_in[3];
    const float* scale = (const float*)d_in[4];

    float* res  = (float*)d_out;                      // [B,H,L,D]
    float* attw = res + (size_t)NBH * LL * DD;        // [B,H,L,L]

    cudaFuncSetAttribute(attn_mma, cudaFuncAttributeMaxDynamicSharedMemorySize, SM_TOTAL);

    dim3 grid(LL / TM, NBH);   // (16, 32)
    attn_mma<<<grid, 256, SM_TOTAL>>>(q, k, v, valid, scale, res, attw);

    fixup_kernel<<<(NBH * (size_t)LL * LL / 4) / 256, 256>>>(attw);
}